// round 9
// baseline (speedup 1.0000x reference)
#include <cuda_runtime.h>

// Winograd F(2x2,3x3) with constant Laplacian filter == direct 3x3 conv of each
// 4x4 tile; row-separable:
//   row r = (a,b,c,d):  x_r = (-b, -c),  y_r = (4b-a-c, 4c-b-d)
//   O_row0 = x_0 + y_1 + x_2 ;  O_row1 = x_1 + y_2 + x_3
//
// Blackwell 256-bit loads: each lane loads one 32B chunk = 2 tile rows.
// Even lane of a pair holds rows {0,1}, odd lane rows {2,3}; 6 SHFLs per warp
// assemble 16 tiles; even lanes store the 2x2 output as one float4 (default
// write-back). ITERS=4 front-batched v8 loads = 128B independent bytes in
// flight per thread (deepest-MLP config; R4/R8 evidence says DRAM% tracks
// in-flight depth).

#define ITERS 4

__device__ __forceinline__ void ld256_cs(const float* p, float r[8]) {
    asm volatile(
        "ld.global.cs.v8.f32 {%0,%1,%2,%3,%4,%5,%6,%7}, [%8];"
        : "=f"(r[0]), "=f"(r[1]), "=f"(r[2]), "=f"(r[3]),
          "=f"(r[4]), "=f"(r[5]), "=f"(r[6]), "=f"(r[7])
        : "l"(p));
}

template <bool GUARDED>
__global__ __launch_bounds__(256) void winograd_kernel(
    const float* __restrict__ in,     // n4*4 floats (4 rows of 4 per tile)
    float4* __restrict__ out4,        // 1 float4 per tile (2x2 row-major)
    int n8)                           // number of 32B chunks (= 2 rows each)
{
    int tid = threadIdx.x;
    int base = blockIdx.x * (256 * ITERS) + tid;   // chunk index

    float v[ITERS][8];

    // Front-batch independent 256-bit loads (MLP_p1 = ITERS)
    #pragma unroll
    for (int k = 0; k < ITERS; k++) {
        int g = base + k * 256;
        if (GUARDED && g >= n8) {
            #pragma unroll
            for (int i = 0; i < 8; i++) v[k][i] = 0.f;
        } else {
            ld256_cs(in + (size_t)g * 8, v[k]);
        }
    }

    const unsigned FULL = 0xFFFFFFFFu;
    bool even = (tid & 1) == 0;

    #pragma unroll
    for (int k = 0; k < ITERS; k++) {
        const float* p = v[k];       // first row  (a,b,c,d) = p[0..3]
        const float* q = v[k] + 4;   // second row           = p[4..7]

        // Row contributions
        float xpa = -p[1], xpb = -p[2];
        float ypa = fmaf(4.0f, p[1], -p[0]) - p[2];
        float ypb = fmaf(4.0f, p[2], -p[1]) - p[3];
        float xqa = -q[1], xqb = -q[2];
        float yqa = fmaf(4.0f, q[1], -q[0]) - q[2];
        float yqb = fmaf(4.0f, q[2], -q[1]) - q[3];

        // Pull odd lane's contributions (its p = tile row2, q = tile row3)
        float sxpa = __shfl_down_sync(FULL, xpa, 1);
        float sxpb = __shfl_down_sync(FULL, xpb, 1);
        float sypa = __shfl_down_sync(FULL, ypa, 1);
        float sypb = __shfl_down_sync(FULL, ypb, 1);
        float sxqa = __shfl_down_sync(FULL, xqa, 1);
        float sxqb = __shfl_down_sync(FULL, xqb, 1);

        int g = base + k * 256;
        bool ok = GUARDED ? (even && g < n8) : even;
        if (ok) {
            float4 o;
            o.x = xpa + yqa + sxpa;   // x_0 + y_1 + x_2
            o.y = xpb + yqb + sxpb;
            o.z = xqa + sypa + sxqa;  // x_1 + y_2 + x_3
            o.w = xqb + sypb + sxqb;
            out4[g >> 1] = o;         // tile = chunk >> 1
        }
    }
}

extern "C" void kernel_launch(void* const* d_in, const int* in_sizes, int n_in,
                              void* d_out, int out_size) {
    const float* x = (const float*)d_in[0];
    float* out = (float*)d_out;
    int n8 = in_sizes[0] / 8;   // 32B chunks (2 rows each)

    const int threads = 256;
    const int chunks_per_block = threads * ITERS;
    int blocks = (n8 + chunks_per_block - 1) / chunks_per_block;

    if (n8 % chunks_per_block == 0) {
        winograd_kernel<false><<<blocks, threads>>>(
            x, (float4*)out, n8);
    } else {
        winograd_kernel<true><<<blocks, threads>>>(
            x, (float4*)out, n8);
    }
}

// round 11
// speedup vs baseline: 1.0729x; 1.0729x over previous
#include <cuda_runtime.h>

// Winograd F(2x2,3x3) with constant Laplacian filter == direct 3x3 conv of each
// 4x4 tile; row-separable:
//   row r = (a,b,c,d):  x_r = (-b, -c),  y_r = (4b-a-c, 4c-b-d)
//   O_row0 = x_0 + y_1 + x_2 ;  O_row1 = x_1 + y_2 + x_3
//
// One lane per input row (float4, coalesced LDG.128); 4-lane groups assemble a
// tile via SHFL. ITERS=4 independent front-batched loads (MLP=4, regs 32,
// occ ~80%) cover DRAM latency; streaming cache hints (data touched once).
// Best measured wall config (R3: 49.9us, DRAM 83.4%); all structural variants
// since (v8 loads, unguarded paths, deeper MLP) shared the same ~6.7TB/s
// streaming ceiling without beating it.

#define ITERS 4

__global__ __launch_bounds__(256) void winograd_kernel(
    const float4* __restrict__ in4,   // n4 float4s (4 per tile, row-major)
    float2* __restrict__ out2,        // 2 float2 per tile
    int n4)
{
    // Block owns a contiguous segment of ITERS*256 rows; thread t handles
    // rows seg + t + k*256. lane&3 == row-within-tile for every k.
    int seg = blockIdx.x * (blockDim.x * ITERS);
    int tid = threadIdx.x;

    float4 m[ITERS];
    int    j[ITERS];

    // Front-batch independent loads (MLP_p1 = ITERS)
    #pragma unroll
    for (int k = 0; k < ITERS; k++) {
        j[k] = seg + k * 256 + tid;
        m[k] = (j[k] < n4) ? __ldcs(&in4[j[k]])
                           : make_float4(0.f, 0.f, 0.f, 0.f);
    }

    const unsigned FULL = 0xFFFFFFFFu;
    int r = tid & 3;

    #pragma unroll
    for (int k = 0; k < ITERS; k++) {
        float x0 = -m[k].y;
        float x1 = -m[k].z;
        float y0 = fmaf(4.0f, m[k].y, -m[k].x) - m[k].z;   // 4b - a - c
        float y1 = fmaf(4.0f, m[k].z, -m[k].y) - m[k].w;   // 4c - b - d

        float z0 = x0 + __shfl_down_sync(FULL, y0, 1);
        float z1 = x1 + __shfl_down_sync(FULL, y1, 1);
        float o0 = z0 + __shfl_down_sync(FULL, x0, 2);
        float o1 = z1 + __shfl_down_sync(FULL, x1, 2);

        if (r < 2 && j[k] < n4) {
            // tile = j>>2, output row r of that tile
            __stcs(&out2[((j[k] >> 2) << 1) | r], make_float2(o0, o1));
        }
    }
}

extern "C" void kernel_launch(void* const* d_in, const int* in_sizes, int n_in,
                              void* d_out, int out_size) {
    const float* x = (const float*)d_in[0];
    float* out = (float*)d_out;
    int n4 = in_sizes[0] / 4;   // number of float4 rows (4 per tile)

    const int threads = 256;
    int rows_per_block = threads * ITERS;
    int blocks = (n4 + rows_per_block - 1) / rows_per_block;
    winograd_kernel<<<blocks, threads>>>(
        (const float4*)x, (float2*)out, n4);
}